// round 14
// baseline (speedup 1.0000x reference)
#include <cuda_runtime.h>
#include <cstdint>

// Problem constants (fixed by the reference)
#define Bp    4
#define Tp    512
#define Kp    256
#define DENC  256
#define DKp   256
#define UN    128
#define TT    4     // timesteps per main block
#define NTHR  256   // 8 warps: warp = (tt, k-half)

// Scratch
__device__ float g_kkT[Bp * UN * Kp];          // 512 KB: kkT[b][u][k]
__device__ float g_e[Bp * Tp * UN];            // 1 MB:  e[b*T+t][u]

// ---------------------------------------------------------------------------
// Prep kernel (R8-proven, byte-identical): grid = 384 blocks, 256 threads.
//   blocks [0,256):  e[row][u] = enc_row @ W1 + b1      (8 rows per block)
//   blocks [256,384): kkT[b][u][k] = (kn[b] @ W2 + b2)^T (8 k per block)
// ---------------------------------------------------------------------------
__global__ void __launch_bounds__(256) prep_kernel(
    const float* __restrict__ kn,
    const float* __restrict__ enc,
    const float* __restrict__ W1,
    const float* __restrict__ b1,
    const float* __restrict__ W2,
    const float* __restrict__ b2)
{
    __shared__ float rowS[8][256];           // 8 KB
    const int tid = threadIdx.x;

    if (blockIdx.x < 256) {
        // ---- e-projection: rows r0..r0+7 of flat [2048][256] encoder ----
        const int r0 = blockIdx.x * 8;
        {
            const float4* src = (const float4*)(enc + (size_t)r0 * DENC);
            float4* dst = (float4*)&rowS[0][0];
            dst[tid] = src[tid];
            dst[tid + 256] = src[tid + 256];
        }
        __syncthreads();

        const int u    = tid & 127;
        const int half = tid >> 7;           // rows half*4 .. half*4+3
        const float bb = b1[u];
        float a0 = bb, a1 = bb, a2 = bb, a3 = bb;
        #pragma unroll 8
        for (int d = 0; d < DENC; d++) {
            const float w = W1[d * UN + u];  // coalesced
            a0 = fmaf(rowS[half * 4 + 0][d], w, a0);
            a1 = fmaf(rowS[half * 4 + 1][d], w, a1);
            a2 = fmaf(rowS[half * 4 + 2][d], w, a2);
            a3 = fmaf(rowS[half * 4 + 3][d], w, a3);
        }
        float* eb = g_e + (size_t)r0 * UN + u;
        eb[(half * 4 + 0) * UN] = a0;
        eb[(half * 4 + 1) * UN] = a1;
        eb[(half * 4 + 2) * UN] = a2;
        eb[(half * 4 + 3) * UN] = a3;
    } else {
        // ---- kkT: b = idx>>5, k0 = (idx&31)*8 ----
        const int idx = blockIdx.x - 256;
        const int b   = idx >> 5;
        const int k0  = (idx & 31) * 8;
        {
            const float4* src = (const float4*)(kn + (size_t)(b * Kp + k0) * DKp);
            float4* dst = (float4*)&rowS[0][0];
            dst[tid] = src[tid];
            dst[tid + 256] = src[tid + 256];
        }
        __syncthreads();

        const int u    = tid & 127;
        const int half = tid >> 7;
        const float bb = b2[u];
        float a0 = bb, a1 = bb, a2 = bb, a3 = bb;
        #pragma unroll 8
        for (int d = 0; d < DKp; d++) {
            const float w = W2[d * UN + u];  // coalesced
            a0 = fmaf(rowS[half * 4 + 0][d], w, a0);
            a1 = fmaf(rowS[half * 4 + 1][d], w, a1);
            a2 = fmaf(rowS[half * 4 + 2][d], w, a2);
            a3 = fmaf(rowS[half * 4 + 3][d], w, a3);
        }
        float4* dst = (float4*)(g_kkT + (size_t)b * UN * Kp + (size_t)u * Kp + k0 + half * 4);
        *dst = make_float4(a0, a1, a2, a3);
    }
}

// ---------------------------------------------------------------------------
// Main kernel, 256 threads (8 warps), grid = 512, 5 blocks/SM (51-reg cap):
//   phase A: COMPLETE scores per warp — warp = (tt, k-half); lane owns
//            k = kh*128 + lane*4 + c over ALL 128 u-rows. No partial-score
//            smem, no combine epilogue, one fewer barrier.
//   softmax: warp-pair combine via tiny smem red buffers
//   phase C: context GEMV, unroll 8, broadcast LDS.128 weights (unchanged)
// ---------------------------------------------------------------------------
__global__ void __launch_bounds__(NTHR, 5) attn_main_kernel(
    const float* __restrict__ kn,
    const float* __restrict__ V,
    float* __restrict__ out)
{
    __shared__ float eS[TT][UN];                    // 2 KB
    __shared__ float Vs[UN];                        // 0.5 KB
    __shared__ __align__(16) float wT[Kp][TT];      // 4 KB, k-major weights
    __shared__ float redMax[8], redSum[8];

    const int tid = threadIdx.x;
    const int b   = blockIdx.x >> 7;                // 0..3
    const int t0  = (blockIdx.x & 127) * TT;        // 0..508

    // Stage e-tile (4x128 = 128 float4) + V (128 floats)
    if (tid < 128)
        ((float4*)&eS[0][0])[tid] =
            ((const float4*)(g_e + (size_t)(b * Tp + t0) * UN))[tid];
    else
        Vs[tid - 128] = V[tid - 128];
    __syncthreads();

    const int warp = tid >> 5;
    const int lane = tid & 31;
    const int tt   = warp >> 1;                     // 0..3
    const int kh   = warp & 1;                      // k-half: k in [kh*128, +128)

    // ---- Phase A: complete scores for this warp's k-half over all 128 u ----
    float s0 = 0.f, s1 = 0.f, s2 = 0.f, s3 = 0.f;  // k = kh*128 + lane*4 + c
    {
        // float4 view: row u at u*64; this lane's quad at + kh*32 + lane
        const float4* kkp = (const float4*)(g_kkT + (size_t)b * UN * Kp)
                          + kh * 32 + lane;
        const float* ep = &eS[tt][0];
        const float* vp = &Vs[0];
        #pragma unroll 4
        for (int u = 0; u < UN; u++) {
            const float4 r = kkp[u * 64];           // LDG.128, L1-hot
            const float e = ep[u];                  // smem broadcast
            const float v = vp[u];                  // smem broadcast
            float th;
            asm("tanh.approx.f32 %0, %1;" : "=f"(th) : "f"(e + r.x)); s0 = fmaf(th, v, s0);
            asm("tanh.approx.f32 %0, %1;" : "=f"(th) : "f"(e + r.y)); s1 = fmaf(th, v, s1);
            asm("tanh.approx.f32 %0, %1;" : "=f"(th) : "f"(e + r.z)); s2 = fmaf(th, v, s2);
            asm("tanh.approx.f32 %0, %1;" : "=f"(th) : "f"(e + r.w)); s3 = fmaf(th, v, s3);
        }
    }

    // ---- Softmax over K=256 split across the warp pair (tt, kh) ----
    float mx = fmaxf(fmaxf(s0, s1), fmaxf(s2, s3));
    #pragma unroll
    for (int o = 16; o > 0; o >>= 1) mx = fmaxf(mx, __shfl_xor_sync(0xffffffffu, mx, o));
    if (lane == 0) redMax[warp] = mx;
    __syncthreads();
    mx = fmaxf(redMax[warp], redMax[warp ^ 1]);

    s0 = __expf(s0 - mx); s1 = __expf(s1 - mx);
    s2 = __expf(s2 - mx); s3 = __expf(s3 - mx);
    float sum = s0 + s1 + s2 + s3;
    #pragma unroll
    for (int o = 16; o > 0; o >>= 1) sum += __shfl_xor_sync(0xffffffffu, sum, o);
    if (lane == 0) redSum[warp] = sum;
    __syncthreads();
    const float inv = 1.0f / (redSum[warp] + redSum[warp ^ 1]);

    // Store k-major weights (4 scalar STS; one-time cost, conflicts tolerable)
    {
        const int kb = kh * 128 + lane * 4;
        wT[kb + 0][tt] = s0 * inv;
        wT[kb + 1][tt] = s1 * inv;
        wT[kb + 2][tt] = s2 * inv;
        wT[kb + 3][tt] = s3 * inv;
    }
    __syncthreads();

    // ---- Phase C: context. Thread owns d = tid, all 4 timesteps, full K ----
    const int d = tid;                              // 0..255 == DKp
    float acc[TT];
    #pragma unroll
    for (int r = 0; r < TT; r++) acc[r] = 0.f;

    const float* knb = kn + (size_t)b * Kp * DKp + d;
    #pragma unroll 8
    for (int k = 0; k < Kp; k++) {
        const float kv = knb[(size_t)k * DKp];      // coalesced LDG, L1/L2 hot
        const float4 w = *(const float4*)&wT[k][0]; // broadcast LDS.128
        acc[0] = fmaf(w.x, kv, acc[0]);
        acc[1] = fmaf(w.y, kv, acc[1]);
        acc[2] = fmaf(w.z, kv, acc[2]);
        acc[3] = fmaf(w.w, kv, acc[3]);
    }
    #pragma unroll
    for (int r = 0; r < TT; r++)
        out[((size_t)(b * Tp + t0 + r)) * DKp + d] = acc[r];
}

// ---------------------------------------------------------------------------
// Harness entry point
// ---------------------------------------------------------------------------
extern "C" void kernel_launch(void* const* d_in, const int* in_sizes, int n_in,
                              void* d_out, int out_size)
{
    const float* kn  = (const float*)d_in[0];  // knowledge_onehot [B,K,D_K]
    const float* enc = (const float*)d_in[1];  // encoder_outputs  [B,T,D_ENC]
    const float* W1  = (const float*)d_in[2];  // [D_ENC,U]
    const float* b1  = (const float*)d_in[3];  // [U]
    const float* W2  = (const float*)d_in[4];  // [D_K,U]
    const float* b2  = (const float*)d_in[5];  // [U]
    const float* V   = (const float*)d_in[6];  // [U,1]
    // d_in[7] = bV: constant shift on scores, softmax-invariant -> ignored.
    float* out = (float*)d_out;                // context [B,T,D_K] fp32

    prep_kernel<<<384, 256>>>(kn, enc, W1, b1, W2, b2);
    attn_main_kernel<<<Bp * (Tp / TT), NTHR>>>(kn, V, out);
}

// round 15
// speedup vs baseline: 1.0064x; 1.0064x over previous
#include <cuda_runtime.h>
#include <cstdint>

// Problem constants (fixed by the reference)
#define Bp    4
#define Tp    512
#define Kp    256
#define DENC  256
#define DKp   256
#define UN    128
#define TT    4     // timesteps per main block
#define NTHR  256   // 8 warps

// Scratch
__device__ float g_kkT[Bp * UN * Kp];          // 512 KB: kkT[b][u][k]
__device__ float g_e[Bp * Tp * UN];            // 1 MB:  e[b*T+t][u]

// ---------------------------------------------------------------------------
// Prep kernel, grid = 256 blocks, 256 threads:
//   blocks [0,128):  e[row][u] = enc_row @ W1 + b1      (16 rows per block;
//                    halves W1 L2 traffic vs 8-row tiles)
//   blocks [128,256): kkT[b][u][k] = (kn[b] @ W2 + b2)^T (8 k per block,
//                    byte-identical to the proven R8 version)
// ---------------------------------------------------------------------------
__global__ void __launch_bounds__(256) prep_kernel(
    const float* __restrict__ kn,
    const float* __restrict__ enc,
    const float* __restrict__ W1,
    const float* __restrict__ b1,
    const float* __restrict__ W2,
    const float* __restrict__ b2)
{
    const int tid = threadIdx.x;

    if (blockIdx.x < 128) {
        // ---- e-projection: rows r0..r0+15 of flat [2048][256] encoder ----
        __shared__ float rowS[16][256];      // 16 KB
        const int r0 = blockIdx.x * 16;
        {
            const float4* src = (const float4*)(enc + (size_t)r0 * DENC);
            float4* dst = (float4*)&rowS[0][0];
            #pragma unroll
            for (int i = 0; i < 4; i++) dst[tid + i * 256] = src[tid + i * 256];
        }
        __syncthreads();

        const int u    = tid & 127;
        const int half = tid >> 7;           // rows half*8 .. half*8+7
        const float bb = b1[u];
        float a[8];
        #pragma unroll
        for (int j = 0; j < 8; j++) a[j] = bb;

        #pragma unroll 4
        for (int d = 0; d < DENC; d++) {
            const float w = W1[d * UN + u];  // coalesced scalar LDG (L1-hot)
            #pragma unroll
            for (int j = 0; j < 8; j++)
                a[j] = fmaf(rowS[half * 8 + j][d], w, a[j]);   // broadcast LDS
        }
        float* eb = g_e + (size_t)r0 * UN + u;
        #pragma unroll
        for (int j = 0; j < 8; j++)
            eb[(half * 8 + j) * UN] = a[j];
    } else {
        // ---- kkT: b = idx>>5, k0 = (idx&31)*8 (R8-proven) ----
        __shared__ float knS[8][DKp];        // 8 KB
        const int idx = blockIdx.x - 128;
        const int b   = idx >> 5;
        const int k0  = (idx & 31) * 8;
        {
            const float4* src = (const float4*)(kn + (size_t)(b * Kp + k0) * DKp);
            float4* dst = (float4*)&knS[0][0];
            dst[tid] = src[tid];
            dst[tid + 256] = src[tid + 256];
        }
        __syncthreads();

        const int u    = tid & 127;
        const int half = tid >> 7;           // rows half*4 .. half*4+3
        const float bb = b2[u];
        float a0 = bb, a1 = bb, a2 = bb, a3 = bb;
        #pragma unroll 8
        for (int d = 0; d < DKp; d++) {
            const float w = W2[d * UN + u];  // coalesced
            a0 = fmaf(knS[half * 4 + 0][d], w, a0);
            a1 = fmaf(knS[half * 4 + 1][d], w, a1);
            a2 = fmaf(knS[half * 4 + 2][d], w, a2);
            a3 = fmaf(knS[half * 4 + 3][d], w, a3);
        }
        float4* dst = (float4*)(g_kkT + (size_t)b * UN * Kp
                                + (size_t)u * Kp + k0 + half * 4);
        *dst = make_float4(a0, a1, a2, a3);
    }
}

// ---------------------------------------------------------------------------
// Main kernel (R8-proven, byte-identical): 256 threads (8 warps), grid = 512,
// 4 blocks/SM for phase diversity:
//   phase A: barrier-free partial scores (warp = (tt, u-half), private rows)
//   softmax: pair combine, weights stored k-major wT[K][4]
//   phase C: context GEMV, unroll 8 for MLP, broadcast LDS.128 weights
// ---------------------------------------------------------------------------
__global__ void __launch_bounds__(NTHR, 4) attn_main_kernel(
    const float* __restrict__ kn,
    const float* __restrict__ V,
    float* __restrict__ out)
{
    __shared__ float eS[TT][UN];                    // 2 KB
    __shared__ float Vs[UN];                        // 0.5 KB
    __shared__ __align__(16) float sP[2][TT][Kp];   // 8 KB partial scores
    __shared__ __align__(16) float wT[Kp][TT];      // 4 KB, k-major weights
    __shared__ float redMax[8], redSum[8];

    const int tid = threadIdx.x;
    const int b   = blockIdx.x >> 7;                // 0..3
    const int t0  = (blockIdx.x & 127) * TT;        // 0..508

    // Stage e-tile (4x128 = 128 float4) + V (128 floats)
    if (tid < 128)
        ((float4*)&eS[0][0])[tid] =
            ((const float4*)(g_e + (size_t)(b * Tp + t0) * UN))[tid];
    else
        Vs[tid - 128] = V[tid - 128];
    __syncthreads();

    const int warp = tid >> 5;
    const int lane = tid & 31;
    const int tt   = warp >> 1;                     // 0..3
    const int uh   = warp & 1;                      // u-half: rows uh*64..+63

    // ---- Phase A: barrier-free partial scores over full K, private u rows --
    float s[8];
    #pragma unroll
    for (int j = 0; j < 8; j++) s[j] = 0.f;
    {
        const float* kkp = g_kkT + (size_t)b * UN * Kp
                         + (size_t)(uh * 64) * Kp + lane * 4;
        const float* ep = &eS[tt][uh * 64];
        const float* vp = &Vs[uh * 64];
        #pragma unroll 4
        for (int u = 0; u < 64; u++) {
            const float e = ep[u];
            const float v = vp[u];
            const float4 r0 = *(const float4*)(kkp + (size_t)u * Kp);
            const float4 r1 = *(const float4*)(kkp + (size_t)u * Kp + 128);
            float th;
            asm("tanh.approx.f32 %0, %1;" : "=f"(th) : "f"(e + r0.x)); s[0] = fmaf(th, v, s[0]);
            asm("tanh.approx.f32 %0, %1;" : "=f"(th) : "f"(e + r0.y)); s[1] = fmaf(th, v, s[1]);
            asm("tanh.approx.f32 %0, %1;" : "=f"(th) : "f"(e + r0.z)); s[2] = fmaf(th, v, s[2]);
            asm("tanh.approx.f32 %0, %1;" : "=f"(th) : "f"(e + r0.w)); s[3] = fmaf(th, v, s[3]);
            asm("tanh.approx.f32 %0, %1;" : "=f"(th) : "f"(e + r1.x)); s[4] = fmaf(th, v, s[4]);
            asm("tanh.approx.f32 %0, %1;" : "=f"(th) : "f"(e + r1.y)); s[5] = fmaf(th, v, s[5]);
            asm("tanh.approx.f32 %0, %1;" : "=f"(th) : "f"(e + r1.z)); s[6] = fmaf(th, v, s[6]);
            asm("tanh.approx.f32 %0, %1;" : "=f"(th) : "f"(e + r1.w)); s[7] = fmaf(th, v, s[7]);
        }
    }
    *(float4*)&sP[uh][tt][lane * 4]       = make_float4(s[0], s[1], s[2], s[3]);
    *(float4*)&sP[uh][tt][128 + lane * 4] = make_float4(s[4], s[5], s[6], s[7]);
    __syncthreads();

    // ---- Combine + softmax. Warp (tt,uh) owns k = uh*128 + lane + 32c ----
    float v4[4];
    {
        const int kb = uh * 128 + lane;
        #pragma unroll
        for (int c = 0; c < 4; c++)
            v4[c] = sP[0][tt][kb + 32 * c] + sP[1][tt][kb + 32 * c];
    }
    float mx = fmaxf(fmaxf(v4[0], v4[1]), fmaxf(v4[2], v4[3]));
    #pragma unroll
    for (int o = 16; o > 0; o >>= 1) mx = fmaxf(mx, __shfl_xor_sync(0xffffffffu, mx, o));
    if (lane == 0) redMax[warp] = mx;
    __syncthreads();
    mx = fmaxf(redMax[warp], redMax[warp ^ 1]);

    float sum = 0.f;
    #pragma unroll
    for (int c = 0; c < 4; c++) { v4[c] = __expf(v4[c] - mx); sum += v4[c]; }
    #pragma unroll
    for (int o = 16; o > 0; o >>= 1) sum += __shfl_xor_sync(0xffffffffu, sum, o);
    if (lane == 0) redSum[warp] = sum;
    __syncthreads();
    const float inv = 1.0f / (redSum[warp] + redSum[warp ^ 1]);
    {
        const int kb = uh * 128 + lane;
        #pragma unroll
        for (int c = 0; c < 4; c++)
            wT[kb + 32 * c][tt] = v4[c] * inv;      // k-major for phase C
    }
    __syncthreads();

    // ---- Phase C: context. Thread owns d = tid, all 4 timesteps, full K ----
    const int d = tid;                              // 0..255 == DKp
    float acc[TT];
    #pragma unroll
    for (int r = 0; r < TT; r++) acc[r] = 0.f;

    const float* knb = kn + (size_t)b * Kp * DKp + d;
    #pragma unroll 8
    for (int k = 0; k < Kp; k++) {
        const float kv = knb[(size_t)k * DKp];      // coalesced LDG, L1/L2 hot
        const float4 w = *(const float4*)&wT[k][0]; // broadcast LDS.128
        acc[0] = fmaf(w.x, kv, acc[0]);
        acc[1] = fmaf(w.y, kv, acc[1]);
        acc[2] = fmaf(w.z, kv, acc[2]);
        acc[3] = fmaf(w.w, kv, acc[3]);
    }
    #pragma unroll
    for (int r = 0; r < TT; r++)
        out[((size_t)(b * Tp + t0 + r)) * DKp + d] = acc[r];
}

// ---------------------------------------------------------------------------
// Harness entry point
// ---------------------------------------------------------------------------
extern "C" void kernel_launch(void* const* d_in, const int* in_sizes, int n_in,
                              void* d_out, int out_size)
{
    const float* kn  = (const float*)d_in[0];  // knowledge_onehot [B,K,D_K]
    const float* enc = (const float*)d_in[1];  // encoder_outputs  [B,T,D_ENC]
    const float* W1  = (const float*)d_in[2];  // [D_ENC,U]
    const float* b1  = (const float*)d_in[3];  // [U]
    const float* W2  = (const float*)d_in[4];  // [D_K,U]
    const float* b2  = (const float*)d_in[5];  // [U]
    const float* V   = (const float*)d_in[6];  // [U,1]
    // d_in[7] = bV: constant shift on scores, softmax-invariant -> ignored.
    float* out = (float*)d_out;                // context [B,T,D_K] fp32

    prep_kernel<<<256, 256>>>(kn, enc, W1, b1, W2, b2);
    attn_main_kernel<<<Bp * (Tp / TT), NTHR>>>(kn, V, out);
}

// round 16
// speedup vs baseline: 1.0552x; 1.0485x over previous
#include <cuda_runtime.h>
#include <cstdint>

// Problem constants (fixed by the reference)
#define Bp    4
#define Tp    512
#define Kp    256
#define DENC  256
#define DKp   256
#define UN    128
#define TT    4     // timesteps per main block
#define NTHR  256   // 8 warps

// Scratch
__device__ float g_kkT[Bp * UN * Kp];          // 512 KB: kkT[b][u][k]
__device__ float g_e[Bp * Tp * UN];            // 1 MB:  e[b*T+t][u]

// ---------------------------------------------------------------------------
// Prep kernel (R8 structure; d-loop unroll 16 for 2x W-load MLP):
// grid = 384 blocks, 256 threads.
//   blocks [0,256):  e[row][u] = enc_row @ W1 + b1      (8 rows per block)
//   blocks [256,384): kkT[b][u][k] = (kn[b] @ W2 + b2)^T (8 k per block)
// ---------------------------------------------------------------------------
__global__ void __launch_bounds__(256) prep_kernel(
    const float* __restrict__ kn,
    const float* __restrict__ enc,
    const float* __restrict__ W1,
    const float* __restrict__ b1,
    const float* __restrict__ W2,
    const float* __restrict__ b2)
{
    __shared__ float rowS[8][256];           // 8 KB
    const int tid = threadIdx.x;

    if (blockIdx.x < 256) {
        // ---- e-projection: rows r0..r0+7 of flat [2048][256] encoder ----
        const int r0 = blockIdx.x * 8;
        {
            const float4* src = (const float4*)(enc + (size_t)r0 * DENC);
            float4* dst = (float4*)&rowS[0][0];
            dst[tid] = src[tid];
            dst[tid + 256] = src[tid + 256];
        }
        __syncthreads();

        const int u    = tid & 127;
        const int half = tid >> 7;           // rows half*4 .. half*4+3
        const float bb = b1[u];
        float a0 = bb, a1 = bb, a2 = bb, a3 = bb;
        #pragma unroll 16
        for (int d = 0; d < DENC; d++) {
            const float w = W1[d * UN + u];  // coalesced; 16 in flight
            a0 = fmaf(rowS[half * 4 + 0][d], w, a0);
            a1 = fmaf(rowS[half * 4 + 1][d], w, a1);
            a2 = fmaf(rowS[half * 4 + 2][d], w, a2);
            a3 = fmaf(rowS[half * 4 + 3][d], w, a3);
        }
        float* eb = g_e + (size_t)r0 * UN + u;
        eb[(half * 4 + 0) * UN] = a0;
        eb[(half * 4 + 1) * UN] = a1;
        eb[(half * 4 + 2) * UN] = a2;
        eb[(half * 4 + 3) * UN] = a3;
    } else {
        // ---- kkT: b = idx>>5, k0 = (idx&31)*8 ----
        const int idx = blockIdx.x - 256;
        const int b   = idx >> 5;
        const int k0  = (idx & 31) * 8;
        {
            const float4* src = (const float4*)(kn + (size_t)(b * Kp + k0) * DKp);
            float4* dst = (float4*)&rowS[0][0];
            dst[tid] = src[tid];
            dst[tid + 256] = src[tid + 256];
        }
        __syncthreads();

        const int u    = tid & 127;
        const int half = tid >> 7;
        const float bb = b2[u];
        float a0 = bb, a1 = bb, a2 = bb, a3 = bb;
        #pragma unroll 16
        for (int d = 0; d < DKp; d++) {
            const float w = W2[d * UN + u];  // coalesced; 16 in flight
            a0 = fmaf(rowS[half * 4 + 0][d], w, a0);
            a1 = fmaf(rowS[half * 4 + 1][d], w, a1);
            a2 = fmaf(rowS[half * 4 + 2][d], w, a2);
            a3 = fmaf(rowS[half * 4 + 3][d], w, a3);
        }
        float4* dst = (float4*)(g_kkT + (size_t)b * UN * Kp + (size_t)u * Kp + k0 + half * 4);
        *dst = make_float4(a0, a1, a2, a3);
    }
}

// ---------------------------------------------------------------------------
// Main kernel (R8-proven, byte-identical): 256 threads (8 warps), grid = 512,
// 4 blocks/SM for phase diversity:
//   phase A: barrier-free partial scores (warp = (tt, u-half), private rows)
//   softmax: pair combine, weights stored k-major wT[K][4]
//   phase C: context GEMV, unroll 8 for MLP, broadcast LDS.128 weights
// ---------------------------------------------------------------------------
__global__ void __launch_bounds__(NTHR, 4) attn_main_kernel(
    const float* __restrict__ kn,
    const float* __restrict__ V,
    float* __restrict__ out)
{
    __shared__ float eS[TT][UN];                    // 2 KB
    __shared__ float Vs[UN];                        // 0.5 KB
    __shared__ __align__(16) float sP[2][TT][Kp];   // 8 KB partial scores
    __shared__ __align__(16) float wT[Kp][TT];      // 4 KB, k-major weights
    __shared__ float redMax[8], redSum[8];

    const int tid = threadIdx.x;
    const int b   = blockIdx.x >> 7;                // 0..3
    const int t0  = (blockIdx.x & 127) * TT;        // 0..508

    // Stage e-tile (4x128 = 128 float4) + V (128 floats)
    if (tid < 128)
        ((float4*)&eS[0][0])[tid] =
            ((const float4*)(g_e + (size_t)(b * Tp + t0) * UN))[tid];
    else
        Vs[tid - 128] = V[tid - 128];
    __syncthreads();

    const int warp = tid >> 5;
    const int lane = tid & 31;
    const int tt   = warp >> 1;                     // 0..3
    const int uh   = warp & 1;                      // u-half: rows uh*64..+63

    // ---- Phase A: barrier-free partial scores over full K, private u rows --
    float s[8];
    #pragma unroll
    for (int j = 0; j < 8; j++) s[j] = 0.f;
    {
        const float* kkp = g_kkT + (size_t)b * UN * Kp
                         + (size_t)(uh * 64) * Kp + lane * 4;
        const float* ep = &eS[tt][uh * 64];
        const float* vp = &Vs[uh * 64];
        #pragma unroll 4
        for (int u = 0; u < 64; u++) {
            const float e = ep[u];
            const float v = vp[u];
            const float4 r0 = *(const float4*)(kkp + (size_t)u * Kp);
            const float4 r1 = *(const float4*)(kkp + (size_t)u * Kp + 128);
            float th;
            asm("tanh.approx.f32 %0, %1;" : "=f"(th) : "f"(e + r0.x)); s[0] = fmaf(th, v, s[0]);
            asm("tanh.approx.f32 %0, %1;" : "=f"(th) : "f"(e + r0.y)); s[1] = fmaf(th, v, s[1]);
            asm("tanh.approx.f32 %0, %1;" : "=f"(th) : "f"(e + r0.z)); s[2] = fmaf(th, v, s[2]);
            asm("tanh.approx.f32 %0, %1;" : "=f"(th) : "f"(e + r0.w)); s[3] = fmaf(th, v, s[3]);
            asm("tanh.approx.f32 %0, %1;" : "=f"(th) : "f"(e + r1.x)); s[4] = fmaf(th, v, s[4]);
            asm("tanh.approx.f32 %0, %1;" : "=f"(th) : "f"(e + r1.y)); s[5] = fmaf(th, v, s[5]);
            asm("tanh.approx.f32 %0, %1;" : "=f"(th) : "f"(e + r1.z)); s[6] = fmaf(th, v, s[6]);
            asm("tanh.approx.f32 %0, %1;" : "=f"(th) : "f"(e + r1.w)); s[7] = fmaf(th, v, s[7]);
        }
    }
    *(float4*)&sP[uh][tt][lane * 4]       = make_float4(s[0], s[1], s[2], s[3]);
    *(float4*)&sP[uh][tt][128 + lane * 4] = make_float4(s[4], s[5], s[6], s[7]);
    __syncthreads();

    // ---- Combine + softmax. Warp (tt,uh) owns k = uh*128 + lane + 32c ----
    float v4[4];
    {
        const int kb = uh * 128 + lane;
        #pragma unroll
        for (int c = 0; c < 4; c++)
            v4[c] = sP[0][tt][kb + 32 * c] + sP[1][tt][kb + 32 * c];
    }
    float mx = fmaxf(fmaxf(v4[0], v4[1]), fmaxf(v4[2], v4[3]));
    #pragma unroll
    for (int o = 16; o > 0; o >>= 1) mx = fmaxf(mx, __shfl_xor_sync(0xffffffffu, mx, o));
    if (lane == 0) redMax[warp] = mx;
    __syncthreads();
    mx = fmaxf(redMax[warp], redMax[warp ^ 1]);

    float sum = 0.f;
    #pragma unroll
    for (int c = 0; c < 4; c++) { v4[c] = __expf(v4[c] - mx); sum += v4[c]; }
    #pragma unroll
    for (int o = 16; o > 0; o >>= 1) sum += __shfl_xor_sync(0xffffffffu, sum, o);
    if (lane == 0) redSum[warp] = sum;
    __syncthreads();
    const float inv = 1.0f / (redSum[warp] + redSum[warp ^ 1]);
    {
        const int kb = uh * 128 + lane;
        #pragma unroll
        for (int c = 0; c < 4; c++)
            wT[kb + 32 * c][tt] = v4[c] * inv;      // k-major for phase C
    }
    __syncthreads();

    // ---- Phase C: context. Thread owns d = tid, all 4 timesteps, full K ----
    const int d = tid;                              // 0..255 == DKp
    float acc[TT];
    #pragma unroll
    for (int r = 0; r < TT; r++) acc[r] = 0.f;

    const float* knb = kn + (size_t)b * Kp * DKp + d;
    #pragma unroll 8
    for (int k = 0; k < Kp; k++) {
        const float kv = knb[(size_t)k * DKp];      // coalesced LDG, L1/L2 hot
        const float4 w = *(const float4*)&wT[k][0]; // broadcast LDS.128
        acc[0] = fmaf(w.x, kv, acc[0]);
        acc[1] = fmaf(w.y, kv, acc[1]);
        acc[2] = fmaf(w.z, kv, acc[2]);
        acc[3] = fmaf(w.w, kv, acc[3]);
    }
    #pragma unroll
    for (int r = 0; r < TT; r++)
        out[((size_t)(b * Tp + t0 + r)) * DKp + d] = acc[r];
}

// ---------------------------------------------------------------------------
// Harness entry point
// ---------------------------------------------------------------------------
extern "C" void kernel_launch(void* const* d_in, const int* in_sizes, int n_in,
                              void* d_out, int out_size)
{
    const float* kn  = (const float*)d_in[0];  // knowledge_onehot [B,K,D_K]
    const float* enc = (const float*)d_in[1];  // encoder_outputs  [B,T,D_ENC]
    const float* W1  = (const float*)d_in[2];  // [D_ENC,U]
    const float* b1  = (const float*)d_in[3];  // [U]
    const float* W2  = (const float*)d_in[4];  // [D_K,U]
    const float* b2  = (const float*)d_in[5];  // [U]
    const float* V   = (const float*)d_in[6];  // [U,1]
    // d_in[7] = bV: constant shift on scores, softmax-invariant -> ignored.
    float* out = (float*)d_out;                // context [B,T,D_K] fp32

    prep_kernel<<<384, 256>>>(kn, enc, W1, b1, W2, b2);
    attn_main_kernel<<<Bp * (Tp / TT), NTHR>>>(kn, V, out);
}